// round 5
// baseline (speedup 1.0000x reference)
#include <cuda_runtime.h>
#include <cuda_bf16.h>
#include <cstdint>
#include <cstddef>

// Problem dims (fixed for Mlp_59983513256146):
//   x  : [4, 4096, 1024] fp32  -> M = 16384 tokens, D = 1024
//   w1 : [4096, 1024], b1: [4096]
//   w2 : [1024, 4096], b2: [1024]
//   out: [4, 4096, 1024] fp32
#define M_TOK 16384
#define DIM_D 1024
#define DIM_H 4096

// ---------------------------------------------------------------------------
// Scratch (device globals -- allocation-free rule)
// ---------------------------------------------------------------------------
__device__ int8_t g_xq [(size_t)M_TOK * DIM_D];          // 16 MB
__device__ int8_t g_w1q[(size_t)DIM_H * DIM_D];          // 4 MB
__device__ int8_t g_w2q[(size_t)DIM_D * DIM_H];          // 4 MB
__device__ float  g_h  [(size_t)M_TOK * DIM_H];          // 256 MB (gelu output, fp32)
__device__ int8_t g_hq [(size_t)M_TOK * DIM_H];          // 64 MB
__device__ unsigned int g_absmax[4];                     // x, w1, w2, gelu(h)

// ---------------------------------------------------------------------------
// absmax reduction (order-independent -> deterministic)
// ---------------------------------------------------------------------------
__global__ void init_absmax_kernel() {
    if (threadIdx.x < 4) g_absmax[threadIdx.x] = 0u;
}

__global__ void absmax_kernel(const float* __restrict__ src, int n4, int slot) {
    const float4* s4 = (const float4*)src;
    float m = 0.0f;
    for (int i = blockIdx.x * blockDim.x + threadIdx.x; i < n4;
         i += gridDim.x * blockDim.x) {
        float4 v = s4[i];
        m = fmaxf(m, fmaxf(fmaxf(fabsf(v.x), fabsf(v.y)),
                           fmaxf(fabsf(v.z), fabsf(v.w))));
    }
    #pragma unroll
    for (int o = 16; o > 0; o >>= 1)
        m = fmaxf(m, __shfl_xor_sync(0xffffffffu, m, o));
    if ((threadIdx.x & 31) == 0)
        atomicMax(&g_absmax[slot], __float_as_uint(m));
}

// ---------------------------------------------------------------------------
// quantize: q = clip(round(v / scale), -127, 127), scale = max(absmax,1e-8)/127
// rintf == round-half-even == jnp.round
// ---------------------------------------------------------------------------
__global__ void quant_kernel(const float* __restrict__ src, int8_t* __restrict__ dst,
                             int n4, int slot) {
    float am = __uint_as_float(g_absmax[slot]);
    float scale = fmaxf(am, 1e-8f) / 127.0f;
    const float4* s4 = (const float4*)src;
    char4* d4 = (char4*)dst;
    for (int i = blockIdx.x * blockDim.x + threadIdx.x; i < n4;
         i += gridDim.x * blockDim.x) {
        float4 v = s4[i];
        float qx = fminf(fmaxf(rintf(v.x / scale), -127.0f), 127.0f);
        float qy = fminf(fmaxf(rintf(v.y / scale), -127.0f), 127.0f);
        float qz = fminf(fmaxf(rintf(v.z / scale), -127.0f), 127.0f);
        float qw = fminf(fmaxf(rintf(v.w / scale), -127.0f), 127.0f);
        d4[i] = make_char4((signed char)(int)qx, (signed char)(int)qy,
                           (signed char)(int)qz, (signed char)(int)qw);
    }
}

// ---------------------------------------------------------------------------
// int8 dp4a GEMM core: C[M,N] = A[M,K] * B[N,K]^T  (both K-major int8)
// Tile 128x128, BK = 64 bytes (16 ints), 256 threads, 8x8 per thread.
// Shared layout k-major: As[kk][row] so fragment loads are LDS.128.
// ---------------------------------------------------------------------------

#define GELU_C 0.70710678118654752440f  // 1/sqrt(2)

__global__ __launch_bounds__(256, 2)
void gemm1_kernel(const float* __restrict__ b1) {
    constexpr int K = DIM_D;   // 1024
    constexpr int N = DIM_H;   // 4096
    __shared__ __align__(16) int As[16][128];
    __shared__ __align__(16) int Bs[16][128];

    const int tid = threadIdx.x;
    const int tx = tid & 15, ty = tid >> 4;
    const int bm = blockIdx.y * 128, bn = blockIdx.x * 128;
    const int8_t* __restrict__ A = g_xq;
    const int8_t* __restrict__ B = g_w1q;

    int acc[8][8];
    #pragma unroll
    for (int i = 0; i < 8; i++)
        #pragma unroll
        for (int j = 0; j < 8; j++) acc[i][j] = 0;

    for (int k0 = 0; k0 < K; k0 += 64) {
        #pragma unroll
        for (int r = 0; r < 2; r++) {
            int id = tid + r * 256;          // 0..511
            int row = id >> 2;               // 0..127
            int kq  = (id & 3) << 2;         // int index 0,4,8,12
            int4 av = *(const int4*)&A[(size_t)(bm + row) * K + k0 + kq * 4];
            As[kq + 0][row] = av.x; As[kq + 1][row] = av.y;
            As[kq + 2][row] = av.z; As[kq + 3][row] = av.w;
            int4 bv = *(const int4*)&B[(size_t)(bn + row) * K + k0 + kq * 4];
            Bs[kq + 0][row] = bv.x; Bs[kq + 1][row] = bv.y;
            Bs[kq + 2][row] = bv.z; Bs[kq + 3][row] = bv.w;
        }
        __syncthreads();
        #pragma unroll
        for (int kk = 0; kk < 16; kk++) {
            int a[8], b[8];
            *(int4*)(a)     = *(const int4*)&As[kk][ty * 8];
            *(int4*)(a + 4) = *(const int4*)&As[kk][ty * 8 + 4];
            *(int4*)(b)     = *(const int4*)&Bs[kk][tx * 8];
            *(int4*)(b + 4) = *(const int4*)&Bs[kk][tx * 8 + 4];
            #pragma unroll
            for (int i = 0; i < 8; i++)
                #pragma unroll
                for (int j = 0; j < 8; j++)
                    acc[i][j] = __dp4a(a[i], b[j], acc[i][j]);
        }
        __syncthreads();
    }

    // epilogue: dequant scale, bias, exact gelu, store fp32 h, track absmax
    float ax = __uint_as_float(g_absmax[0]);
    float aw = __uint_as_float(g_absmax[1]);
    float s = (fmaxf(ax, 1e-8f) / 127.0f) * (fmaxf(aw, 1e-8f) / 127.0f);

    float bias[8];
    #pragma unroll
    for (int j = 0; j < 8; j++) bias[j] = b1[bn + tx * 8 + j];

    float lmax = 0.0f;
    #pragma unroll
    for (int i = 0; i < 8; i++) {
        int m = bm + ty * 8 + i;
        float vals[8];
        #pragma unroll
        for (int j = 0; j < 8; j++) {
            float v = (float)acc[i][j] * s + bias[j];
            float g = 0.5f * v * (1.0f + erff(v * GELU_C));
            vals[j] = g;
            lmax = fmaxf(lmax, fabsf(g));
        }
        float* dst = &g_h[(size_t)m * N + bn + tx * 8];
        *(float4*)(dst)     = make_float4(vals[0], vals[1], vals[2], vals[3]);
        *(float4*)(dst + 4) = make_float4(vals[4], vals[5], vals[6], vals[7]);
    }
    #pragma unroll
    for (int o = 16; o > 0; o >>= 1)
        lmax = fmaxf(lmax, __shfl_xor_sync(0xffffffffu, lmax, o));
    if ((tid & 31) == 0)
        atomicMax(&g_absmax[3], __float_as_uint(lmax));
}

__global__ __launch_bounds__(256, 2)
void gemm2_kernel(const float* __restrict__ b2, float* __restrict__ out) {
    constexpr int K = DIM_H;   // 4096
    constexpr int N = DIM_D;   // 1024
    __shared__ __align__(16) int As[16][128];
    __shared__ __align__(16) int Bs[16][128];

    const int tid = threadIdx.x;
    const int tx = tid & 15, ty = tid >> 4;
    const int bm = blockIdx.y * 128, bn = blockIdx.x * 128;
    const int8_t* __restrict__ A = g_hq;
    const int8_t* __restrict__ B = g_w2q;

    int acc[8][8];
    #pragma unroll
    for (int i = 0; i < 8; i++)
        #pragma unroll
        for (int j = 0; j < 8; j++) acc[i][j] = 0;

    for (int k0 = 0; k0 < K; k0 += 64) {
        #pragma unroll
        for (int r = 0; r < 2; r++) {
            int id = tid + r * 256;
            int row = id >> 2;
            int kq  = (id & 3) << 2;
            int4 av = *(const int4*)&A[(size_t)(bm + row) * K + k0 + kq * 4];
            As[kq + 0][row] = av.x; As[kq + 1][row] = av.y;
            As[kq + 2][row] = av.z; As[kq + 3][row] = av.w;
            int4 bv = *(const int4*)&B[(size_t)(bn + row) * K + k0 + kq * 4];
            Bs[kq + 0][row] = bv.x; Bs[kq + 1][row] = bv.y;
            Bs[kq + 2][row] = bv.z; Bs[kq + 3][row] = bv.w;
        }
        __syncthreads();
        #pragma unroll
        for (int kk = 0; kk < 16; kk++) {
            int a[8], b[8];
            *(int4*)(a)     = *(const int4*)&As[kk][ty * 8];
            *(int4*)(a + 4) = *(const int4*)&As[kk][ty * 8 + 4];
            *(int4*)(b)     = *(const int4*)&Bs[kk][tx * 8];
            *(int4*)(b + 4) = *(const int4*)&Bs[kk][tx * 8 + 4];
            #pragma unroll
            for (int i = 0; i < 8; i++)
                #pragma unroll
                for (int j = 0; j < 8; j++)
                    acc[i][j] = __dp4a(a[i], b[j], acc[i][j]);
        }
        __syncthreads();
    }

    float ah = __uint_as_float(g_absmax[3]);
    float aw = __uint_as_float(g_absmax[2]);
    float s = (fmaxf(ah, 1e-8f) / 127.0f) * (fmaxf(aw, 1e-8f) / 127.0f);

    float bias[8];
    #pragma unroll
    for (int j = 0; j < 8; j++) bias[j] = b2[bn + tx * 8 + j];

    #pragma unroll
    for (int i = 0; i < 8; i++) {
        int m = bm + ty * 8 + i;
        float vals[8];
        #pragma unroll
        for (int j = 0; j < 8; j++)
            vals[j] = (float)acc[i][j] * s + bias[j];
        float* dst = &out[(size_t)m * N + bn + tx * 8];
        *(float4*)(dst)     = make_float4(vals[0], vals[1], vals[2], vals[3]);
        *(float4*)(dst + 4) = make_float4(vals[4], vals[5], vals[6], vals[7]);
    }
}

// quantize gelu(h) using slot 3 absmax
__global__ void quant_h_kernel(int n4) {
    float am = __uint_as_float(g_absmax[3]);
    float scale = fmaxf(am, 1e-8f) / 127.0f;
    const float4* s4 = (const float4*)g_h;
    char4* d4 = (char4*)g_hq;
    for (int i = blockIdx.x * blockDim.x + threadIdx.x; i < n4;
         i += gridDim.x * blockDim.x) {
        float4 v = s4[i];
        float qx = fminf(fmaxf(rintf(v.x / scale), -127.0f), 127.0f);
        float qy = fminf(fmaxf(rintf(v.y / scale), -127.0f), 127.0f);
        float qz = fminf(fmaxf(rintf(v.z / scale), -127.0f), 127.0f);
        float qw = fminf(fmaxf(rintf(v.w / scale), -127.0f), 127.0f);
        d4[i] = make_char4((signed char)(int)qx, (signed char)(int)qy,
                           (signed char)(int)qz, (signed char)(int)qw);
    }
}

// ---------------------------------------------------------------------------
// launch
// ---------------------------------------------------------------------------
extern "C" void kernel_launch(void* const* d_in, const int* in_sizes, int n_in,
                              void* d_out, int out_size) {
    const float* x  = (const float*)d_in[0];
    const float* w1 = (const float*)d_in[1];
    const float* b1 = (const float*)d_in[2];
    const float* w2 = (const float*)d_in[3];
    const float* b2 = (const float*)d_in[4];
    float* out = (float*)d_out;

    const int nx  = M_TOK * DIM_D;      // 16.78M
    const int nw1 = DIM_H * DIM_D;      // 4.19M
    const int nw2 = DIM_D * DIM_H;      // 4.19M
    const int nh  = M_TOK * DIM_H;      // 67.1M

    int8_t* d_xq;  cudaGetSymbolAddress((void**)&d_xq,  g_xq);
    int8_t* d_w1q; cudaGetSymbolAddress((void**)&d_w1q, g_w1q);
    int8_t* d_w2q; cudaGetSymbolAddress((void**)&d_w2q, g_w2q);

    init_absmax_kernel<<<1, 32>>>();

    absmax_kernel<<<2048, 256>>>(x,  nx  / 4, 0);
    absmax_kernel<<<1024, 256>>>(w1, nw1 / 4, 1);
    absmax_kernel<<<1024, 256>>>(w2, nw2 / 4, 2);

    quant_kernel<<<2048, 256>>>(x,  d_xq,  nx  / 4, 0);
    quant_kernel<<<1024, 256>>>(w1, d_w1q, nw1 / 4, 1);
    quant_kernel<<<1024, 256>>>(w2, d_w2q, nw2 / 4, 2);

    // GEMM1: [16384,1024] x [4096,1024]^T -> gelu -> g_h (+ absmax slot 3)
    gemm1_kernel<<<dim3(DIM_H / 128, M_TOK / 128), 256>>>(b1);

    quant_h_kernel<<<4096, 256>>>(nh / 4);

    // GEMM2: [16384,4096] x [1024,4096]^T -> out
    gemm2_kernel<<<dim3(DIM_D / 128, M_TOK / 128), 256>>>(b2, out);
}

// round 7
// speedup vs baseline: 1.0858x; 1.0858x over previous
#include <cuda_runtime.h>
#include <cuda_bf16.h>
#include <cstdint>
#include <cstddef>

#define M_TOK 16384
#define DIM_D 1024
#define DIM_H 4096

// ---------------------------------------------------------------------------
// Scratch (device globals -- allocation-free rule)
// ---------------------------------------------------------------------------
__device__ int8_t g_xq [(size_t)M_TOK * DIM_D];          // 16 MB
__device__ int8_t g_w1q[(size_t)DIM_H * DIM_D];          // 4 MB
__device__ int8_t g_w2q[(size_t)DIM_D * DIM_H];          // 4 MB
__device__ float  g_h  [(size_t)M_TOK * DIM_H];          // 256 MB (gelu out, fp32)
__device__ int8_t g_hq [(size_t)M_TOK * DIM_H];          // 64 MB
__device__ unsigned int g_absmax[4];                     // x, w1, w2, gelu(h)

// ---------------------------------------------------------------------------
// PTX helpers -- base sm_103-safe only (mma.sync / ldmatrix / cp.async)
// ---------------------------------------------------------------------------
__device__ __forceinline__ uint32_t smem_u32(const void* p) {
    uint32_t a;
    asm("{ .reg .u64 t; cvta.to.shared.u64 t, %1; cvt.u32.u64 %0, t; }"
        : "=r"(a) : "l"(p));
    return a;
}
#define LDSM4(r0, r1, r2, r3, addr) \
    asm volatile("ldmatrix.sync.aligned.m8n8.x4.shared.b16 {%0,%1,%2,%3}, [%4];" \
                 : "=r"(r0), "=r"(r1), "=r"(r2), "=r"(r3) : "r"(addr))
#define CPASYNC16(d, s) \
    asm volatile("cp.async.cg.shared.global [%0], [%1], 16;" \
                 :: "r"(d), "l"(s) : "memory")
#define CPCOMMIT() asm volatile("cp.async.commit_group;" ::: "memory")
#define CPWAIT(n)  asm volatile("cp.async.wait_group %0;" :: "n"(n) : "memory")

__device__ __forceinline__ void mma_s8(int* c, const uint32_t* a, const uint32_t* b) {
    asm volatile(
        "mma.sync.aligned.m16n8k32.row.col.s32.s8.s8.s32 "
        "{%0,%1,%2,%3}, {%4,%5,%6,%7}, {%8,%9}, {%0,%1,%2,%3};"
        : "+r"(c[0]), "+r"(c[1]), "+r"(c[2]), "+r"(c[3])
        : "r"(a[0]), "r"(a[1]), "r"(a[2]), "r"(a[3]), "r"(b[0]), "r"(b[1]));
}

// ---------------------------------------------------------------------------
// absmax + int8 quantize (identical numerics to the passing R5 kernel)
// ---------------------------------------------------------------------------
__global__ void init_absmax_kernel() {
    if (threadIdx.x < 4) g_absmax[threadIdx.x] = 0u;
}

__global__ void absmax_kernel(const float* __restrict__ src, int n4, int slot) {
    const float4* s4 = (const float4*)src;
    float m = 0.0f;
    for (int i = blockIdx.x * blockDim.x + threadIdx.x; i < n4;
         i += gridDim.x * blockDim.x) {
        float4 v = s4[i];
        m = fmaxf(m, fmaxf(fmaxf(fabsf(v.x), fabsf(v.y)),
                           fmaxf(fabsf(v.z), fabsf(v.w))));
    }
    #pragma unroll
    for (int o = 16; o > 0; o >>= 1)
        m = fmaxf(m, __shfl_xor_sync(0xffffffffu, m, o));
    if ((threadIdx.x & 31) == 0)
        atomicMax(&g_absmax[slot], __float_as_uint(m));
}

__global__ void quant_kernel(const float* __restrict__ src, int8_t* __restrict__ dst,
                             int n4, int slot) {
    float am = __uint_as_float(g_absmax[slot]);
    float scale = fmaxf(am, 1e-8f) / 127.0f;
    const float4* s4 = (const float4*)src;
    char4* d4 = (char4*)dst;
    for (int i = blockIdx.x * blockDim.x + threadIdx.x; i < n4;
         i += gridDim.x * blockDim.x) {
        float4 v = s4[i];
        float qx = fminf(fmaxf(rintf(v.x / scale), -127.0f), 127.0f);
        float qy = fminf(fmaxf(rintf(v.y / scale), -127.0f), 127.0f);
        float qz = fminf(fmaxf(rintf(v.z / scale), -127.0f), 127.0f);
        float qw = fminf(fmaxf(rintf(v.w / scale), -127.0f), 127.0f);
        d4[i] = make_char4((signed char)(int)qx, (signed char)(int)qy,
                           (signed char)(int)qz, (signed char)(int)qw);
    }
}

__global__ void quant_h_kernel(int n4) {
    float am = __uint_as_float(g_absmax[3]);
    float scale = fmaxf(am, 1e-8f) / 127.0f;
    const float4* s4 = (const float4*)g_h;
    char4* d4 = (char4*)g_hq;
    for (int i = blockIdx.x * blockDim.x + threadIdx.x; i < n4;
         i += gridDim.x * blockDim.x) {
        float4 v = s4[i];
        float qx = fminf(fmaxf(rintf(v.x / scale), -127.0f), 127.0f);
        float qy = fminf(fmaxf(rintf(v.y / scale), -127.0f), 127.0f);
        float qz = fminf(fmaxf(rintf(v.z / scale), -127.0f), 127.0f);
        float qw = fminf(fmaxf(rintf(v.w / scale), -127.0f), 127.0f);
        d4[i] = make_char4((signed char)(int)qx, (signed char)(int)qy,
                           (signed char)(int)qz, (signed char)(int)qw);
    }
}

// ---------------------------------------------------------------------------
// IMMA GEMM: C[M,Ng] = A[M,K] * B[Ng,K]^T  (both int8 K-major)
// Block 128x128, 8 warps of 64x32, mma.m16n8k32, cp.async 2-stage pipeline.
// SMEM row stride 80B -> ldmatrix conflict-free ((5r + c16) mod 8 is bijective).
// ---------------------------------------------------------------------------
#define GELU_C 0.70710678118654752440f
#define SSTR 80

template<int K, bool GELU>
__global__ void __launch_bounds__(256)
gemm_imma(const int8_t* __restrict__ A, const int8_t* __restrict__ B,
          const float* __restrict__ bias, float* __restrict__ Cout, int Ng,
          int slotA, int slotB) {
    __shared__ __align__(16) int8_t As[2][128 * SSTR];
    __shared__ __align__(16) int8_t Bs[2][128 * SSTR];

    const int tid = threadIdx.x;
    const int wid = tid >> 5, lane = tid & 31;
    const int bm = blockIdx.y * 128, bn = blockIdx.x * 128;
    const int wm = (wid & 1) * 64, wn = (wid >> 1) * 32;
    constexpr int NCH = K / 64;

    int acc[4][4][4];
    #pragma unroll
    for (int i = 0; i < 4; i++)
        #pragma unroll
        for (int j = 0; j < 4; j++)
            #pragma unroll
            for (int r = 0; r < 4; r++) acc[i][j][r] = 0;

    // global -> smem stage copy (cp.async, 16B per op, 4 ops/thread)
    auto issue = [&](int ch, int st) {
        const int k0 = ch * 64;
        #pragma unroll
        for (int it = 0; it < 2; it++) {
            int c = tid + it * 256;           // 0..511
            int row = c >> 2, c16 = (c & 3) * 16;
            uint32_t da = smem_u32(&As[st][row * SSTR + c16]);
            CPASYNC16(da, A + (size_t)(bm + row) * K + k0 + c16);
            uint32_t db = smem_u32(&Bs[st][row * SSTR + c16]);
            CPASYNC16(db, B + (size_t)(bn + row) * K + k0 + c16);
        }
    };

    issue(0, 0);
    CPCOMMIT();

    for (int ch = 0; ch < NCH; ch++) {
        const int st = ch & 1;
        if (ch + 1 < NCH) {
            issue(ch + 1, st ^ 1);
            CPCOMMIT();
            CPWAIT(1);
        } else {
            CPWAIT(0);
        }
        __syncthreads();

        // two k-steps of 32 within the 64B chunk
        #pragma unroll
        for (int ks = 0; ks < 2; ks++) {
            const int kb = ks * 32;
            const int r8 = lane & 7, mg = lane >> 3;   // ldmatrix ptr group

            uint32_t a[4][4];
            #pragma unroll
            for (int i = 0; i < 4; i++) {
                uint32_t addr = smem_u32(
                    &As[st][(wm + i * 16 + (mg & 1) * 8 + r8) * SSTR + kb + (mg >> 1) * 16]);
                LDSM4(a[i][0], a[i][1], a[i][2], a[i][3], addr);
            }
            uint32_t b[4][2];
            #pragma unroll
            for (int jp = 0; jp < 2; jp++) {
                uint32_t addr = smem_u32(
                    &Bs[st][(wn + jp * 16 + (mg >> 1) * 8 + r8) * SSTR + kb + (mg & 1) * 16]);
                uint32_t r0, r1, r2, r3;
                LDSM4(r0, r1, r2, r3, addr);
                b[jp * 2][0] = r0; b[jp * 2][1] = r1;
                b[jp * 2 + 1][0] = r2; b[jp * 2 + 1][1] = r3;
            }
            #pragma unroll
            for (int i = 0; i < 4; i++)
                #pragma unroll
                for (int j = 0; j < 4; j++)
                    mma_s8(acc[i][j], a[i], b[j]);
        }
        __syncthreads();
    }

    // ---- epilogue: dequant + bias (+ exact gelu + absmax) -> fp32 ----
    const float sA = fmaxf(__uint_as_float(g_absmax[slotA]), 1e-8f) / 127.0f;
    const float sB = fmaxf(__uint_as_float(g_absmax[slotB]), 1e-8f) / 127.0f;
    const float s = sA * sB;
    const int r4 = lane >> 2, c2 = (lane & 3) * 2;
    float lmax = 0.0f;

    #pragma unroll
    for (int i = 0; i < 4; i++) {
        const int row0 = bm + wm + i * 16 + r4;
        #pragma unroll
        for (int j = 0; j < 4; j++) {
            const int n = bn + wn + j * 8 + c2;
            const float b0 = __ldg(&bias[n]), b1 = __ldg(&bias[n + 1]);
            float v00 = (float)acc[i][j][0] * s + b0;
            float v01 = (float)acc[i][j][1] * s + b1;
            float v10 = (float)acc[i][j][2] * s + b0;
            float v11 = (float)acc[i][j][3] * s + b1;
            if (GELU) {
                v00 = 0.5f * v00 * (1.0f + erff(v00 * GELU_C));
                v01 = 0.5f * v01 * (1.0f + erff(v01 * GELU_C));
                v10 = 0.5f * v10 * (1.0f + erff(v10 * GELU_C));
                v11 = 0.5f * v11 * (1.0f + erff(v11 * GELU_C));
                lmax = fmaxf(lmax, fmaxf(fmaxf(fabsf(v00), fabsf(v01)),
                                         fmaxf(fabsf(v10), fabsf(v11))));
            }
            *(float2*)&Cout[(size_t)row0 * Ng + n]       = make_float2(v00, v01);
            *(float2*)&Cout[(size_t)(row0 + 8) * Ng + n] = make_float2(v10, v11);
        }
    }
    if (GELU) {
        #pragma unroll
        for (int o = 16; o > 0; o >>= 1)
            lmax = fmaxf(lmax, __shfl_xor_sync(0xffffffffu, lmax, o));
        if (lane == 0) atomicMax(&g_absmax[3], __float_as_uint(lmax));
    }
}

// ---------------------------------------------------------------------------
// launch
// ---------------------------------------------------------------------------
extern "C" void kernel_launch(void* const* d_in, const int* in_sizes, int n_in,
                              void* d_out, int out_size) {
    const float* x  = (const float*)d_in[0];
    const float* w1 = (const float*)d_in[1];
    const float* b1 = (const float*)d_in[2];
    const float* w2 = (const float*)d_in[3];
    const float* b2 = (const float*)d_in[4];
    float* out = (float*)d_out;

    const int nx  = M_TOK * DIM_D;
    const int nw1 = DIM_H * DIM_D;
    const int nw2 = DIM_D * DIM_H;
    const int nh  = M_TOK * DIM_H;

    int8_t *d_xq, *d_w1q, *d_w2q, *d_hq;
    float* d_h;
    cudaGetSymbolAddress((void**)&d_xq,  g_xq);
    cudaGetSymbolAddress((void**)&d_w1q, g_w1q);
    cudaGetSymbolAddress((void**)&d_w2q, g_w2q);
    cudaGetSymbolAddress((void**)&d_hq,  g_hq);
    cudaGetSymbolAddress((void**)&d_h,   g_h);

    init_absmax_kernel<<<1, 32>>>();

    absmax_kernel<<<2048, 256>>>(x,  nx  / 4, 0);
    absmax_kernel<<<1024, 256>>>(w1, nw1 / 4, 1);
    absmax_kernel<<<1024, 256>>>(w2, nw2 / 4, 2);

    quant_kernel<<<2048, 256>>>(x,  d_xq,  nx  / 4, 0);
    quant_kernel<<<1024, 256>>>(w1, d_w1q, nw1 / 4, 1);
    quant_kernel<<<1024, 256>>>(w2, d_w2q, nw2 / 4, 2);

    // GEMM1: [16384,1024] x [4096,1024]^T -> +b1 -> gelu -> g_h, absmax slot3
    gemm_imma<DIM_D, true><<<dim3(DIM_H / 128, M_TOK / 128), 256>>>(
        d_xq, d_w1q, b1, d_h, DIM_H, 0, 1);

    quant_h_kernel<<<4096, 256>>>(nh / 4);

    // GEMM2: [16384,4096] x [1024,4096]^T -> +b2 -> out
    gemm_imma<DIM_H, false><<<dim3(DIM_D / 128, M_TOK / 128), 256>>>(
        d_hq, d_w2q, b2, out, DIM_D, 3, 2);
}